// round 12
// baseline (speedup 1.0000x reference)
#include <cuda_runtime.h>
#include <cuda_fp16.h>

#define DM    1024
#define NH    16
#define HD    64
#define BATCH 2
#define SEQ   2048
#define MROWS (BATCH*SEQ)      // 4096

// log2(e)/sqrt(64) folded into K: scores come out in log2 units
#define KSCALE 0.1803368801111137f

// Scratch (device globals, fp16 — no allocation allowed)
__device__ __half g_q  [MROWS*DM];
__device__ __half g_k  [MROWS*DM];
__device__ __half g_v  [MROWS*DM];
__device__ __half g_c1 [MROWS*DM];
__device__ __half g_c2 [MROWS*DM];
__device__ __half g_xh [MROWS*DM];       // x   -> fp16
__device__ __half g_wh [3*DM*DM];        // Wqkv -> fp16
__device__ __half g_oh [DM*DM];          // out_w -> fp16

__device__ __forceinline__ unsigned pack2(float a, float b) {
    __half2 h = __floats2half2_rn(a, b);
    return *(unsigned*)&h;
}
__device__ __forceinline__ unsigned su32(const void* p) {
    return (unsigned)__cvta_generic_to_shared(p);
}
__device__ __forceinline__ float ex2f(float x) {
    float r; asm("ex2.approx.f32 %0, %1;" : "=f"(r) : "f"(x)); return r;
}
__device__ __forceinline__ unsigned hex2(unsigned x) {
    unsigned r; asm("ex2.approx.f16x2 %0, %1;" : "=r"(r) : "r"(x)); return r;
}
__device__ __forceinline__ void mma16(float* d, const unsigned* a,
                                      unsigned b0, unsigned b1) {
    asm volatile(
        "mma.sync.aligned.m16n8k16.row.col.f32.f16.f16.f32 "
        "{%0,%1,%2,%3}, {%4,%5,%6,%7}, {%8,%9}, {%0,%1,%2,%3};"
        : "+f"(d[0]), "+f"(d[1]), "+f"(d[2]), "+f"(d[3])
        : "r"(a[0]), "r"(a[1]), "r"(a[2]), "r"(a[3]), "r"(b0), "r"(b1));
}
__device__ __forceinline__ void ldsm4(unsigned& r0, unsigned& r1,
                                      unsigned& r2, unsigned& r3, unsigned a) {
    asm volatile("ldmatrix.sync.aligned.m8n8.x4.shared.b16 {%0,%1,%2,%3}, [%4];"
        : "=r"(r0), "=r"(r1), "=r"(r2), "=r"(r3) : "r"(a));
}
__device__ __forceinline__ void ldsm4t(unsigned& r0, unsigned& r1,
                                       unsigned& r2, unsigned& r3, unsigned a) {
    asm volatile("ldmatrix.sync.aligned.m8n8.x4.trans.shared.b16 {%0,%1,%2,%3}, [%4];"
        : "=r"(r0), "=r"(r1), "=r"(r2), "=r"(r3) : "r"(a));
}
// .cg: bypass L1 on the fill — tiles are stream-once, never re-read via L1
__device__ __forceinline__ void cpa16(unsigned dst, const void* src) {
    asm volatile("cp.async.cg.shared.global [%0], [%1], 16;"
        :: "r"(dst), "l"(src));
}
__device__ __forceinline__ void cpa_commit() {
    asm volatile("cp.async.commit_group;");
}
__device__ __forceinline__ void cpa_wait0() {
    asm volatile("cp.async.wait_group 0;" ::: "memory");
}
__device__ __forceinline__ void cpa_wait1() {
    asm volatile("cp.async.wait_group 1;" ::: "memory");
}

// ---------------------------------------------------------------------------
// f32 -> fp16 bulk convert (8 elems/thread)
// ---------------------------------------------------------------------------
__global__ __launch_bounds__(256)
void f2h(const float* __restrict__ in, __half* __restrict__ out, int n)
{
    int i = (blockIdx.x * 256 + threadIdx.x) * 8;
    if (i >= n) return;
    float4 a = *(const float4*)(in + i);
    float4 b = *(const float4*)(in + i + 4);
    *(uint4*)(out + i) = make_uint4(pack2(a.x, a.y), pack2(a.z, a.w),
                                    pack2(b.x, b.y), pack2(b.z, b.w));
}

// ---------------------------------------------------------------------------
// All-fp16 cp.async 3-stage pipelined GEMM: C[M,N] = A @ B^T + bias
// MODE 0: f32 write to C; MODE 1: qkv scatter to fp16 buffers (k * KSCALE)
// CTA 128x128, 256 threads (8 warps 4x2), warp tile 32x64, kc=64.
// kc=64 halves barrier frequency vs round-11 (barrier cost was ~30% of loop).
// ---------------------------------------------------------------------------
#define GST 72                         // half stride (64 + pad 8)
#define GSOF (128*GST*2)               // bytes per stage per matrix (18.4 KB)
#define GEMM_SMEM (2*3*128*GST*2)      // 110.6 KB (3 stages, A+B) -> 2 CTAs/SM

template<int MODE>
__global__ __launch_bounds__(256, 2)
void gemm_hh(const __half* __restrict__ A, const __half* __restrict__ B,
             const float* __restrict__ bias, float* __restrict__ C,
             int M, int N, int K,
             __half* __restrict__ qo, __half* __restrict__ ko,
             __half* __restrict__ vo)
{
    extern __shared__ __half gsm[];
    __half* As = gsm;                  // [3][128][GST]
    __half* Bs = gsm + 3 * 128 * GST;

    const int tid = threadIdx.x;
    const int wid = tid >> 5, lane = tid & 31;
    const int lg = lane >> 2, la3 = lane & 3;
    const int wm = wid & 3, wn = wid >> 2;          // warp grid 4x2
    const int bm = blockIdx.y * 128, bn = blockIdx.x * 128;

    float acc[2][8][4];
    #pragma unroll
    for (int mt = 0; mt < 2; mt++)
        #pragma unroll
        for (int nt = 0; nt < 8; nt++)
            #pragma unroll
            for (int i = 0; i < 4; i++) acc[mt][nt][i] = 0.f;

    const int lrow = tid >> 1, lcolh = (tid & 1) * 32;  // 128 rows x 64 halfs
    const __half* Ap = A + (size_t)(bm + lrow) * K + lcolh;
    const __half* Bp = B + (size_t)(bn + lrow) * K + lcolh;
    const unsigned adst = su32(As + lrow * GST + lcolh);
    const unsigned bdst = su32(Bs + lrow * GST + lcolh);

    // prologue: stages 0 and 1 (4 x 16B per matrix per thread per stage)
    #pragma unroll
    for (int st = 0; st < 2; st++) {
        const int k0 = 64 * st;
        #pragma unroll
        for (int c = 0; c < 4; c++) {
            cpa16(adst + st * GSOF + c * 16, Ap + k0 + c * 8);
            cpa16(bdst + st * GSOF + c * 16, Bp + k0 + c * 8);
        }
        cpa_commit();
    }

    const unsigned a_frag = su32(As + (wm * 32 + (lane & 15)) * GST + (lane >> 4) * 8);
    const unsigned b_frag = su32(Bs + (wn * 64 + ((lane & 7) + ((lane >> 4) << 3))) * GST)
                            + (lane & 8) * 2;

    const int NIT = K / 64;
    int s = 0;
    for (int it = 0; it < NIT; it++) {
        cpa_wait1();
        __syncthreads();
        const unsigned soff = s * GSOF;

        #pragma unroll
        for (int ks = 0; ks < 4; ks++) {
            unsigned af[2][4];
            #pragma unroll
            for (int mt = 0; mt < 2; mt++)
                ldsm4(af[mt][0], af[mt][1], af[mt][2], af[mt][3],
                      a_frag + soff + (mt * 16 * GST + ks * 16) * 2);
            #pragma unroll
            for (int n16 = 0; n16 < 4; n16++) {
                unsigned r0, r1, r2, r3;
                ldsm4(r0, r1, r2, r3,
                      b_frag + soff + (n16 * 16 * GST + ks * 16) * 2);
                #pragma unroll
                for (int mt = 0; mt < 2; mt++) {
                    mma16(acc[mt][2 * n16    ], af[mt], r0, r1);
                    mma16(acc[mt][2 * n16 + 1], af[mt], r2, r3);
                }
            }
        }

        if (it + 2 < NIT) {       // stream stage it+2 into slot (it+2)%3
            int ns = s + 2; if (ns >= 3) ns -= 3;
            const int k0 = 64 * (it + 2);
            #pragma unroll
            for (int c = 0; c < 4; c++) {
                cpa16(adst + ns * GSOF + c * 16, Ap + k0 + c * 8);
                cpa16(bdst + ns * GSOF + c * 16, Bp + k0 + c * 8);
            }
        }
        cpa_commit();
        if (++s == 3) s = 0;
    }

    #pragma unroll
    for (int mt = 0; mt < 2; mt++)
        #pragma unroll
        for (int nt = 0; nt < 8; nt++) {
            const int row0 = bm + wm * 32 + mt * 16 + lg;
            const int col  = bn + wn * 64 + nt * 8 + 2 * la3;
            float v0 = acc[mt][nt][0] + bias[col];
            float v1 = acc[mt][nt][1] + bias[col + 1];
            float v2 = acc[mt][nt][2] + bias[col];
            float v3 = acc[mt][nt][3] + bias[col + 1];
            if (MODE == 0) {
                *(float2*)&C[(size_t)row0 * N + col]       = make_float2(v0, v1);
                *(float2*)&C[(size_t)(row0 + 8) * N + col] = make_float2(v2, v3);
            } else {
                const int g = col >> 10, rem = col & 1023;
                if (g == 1) { v0 *= KSCALE; v1 *= KSCALE; v2 *= KSCALE; v3 *= KSCALE; }
                __half* dst = (g == 0) ? qo : (g == 1) ? ko : vo;
                *(unsigned*)&dst[(size_t)row0 * DM + rem]       = pack2(v0, v1);
                *(unsigned*)&dst[(size_t)(row0 + 8) * DM + rem] = pack2(v2, v3);
            }
        }
}

// ---------------------------------------------------------------------------
// FP16 tensor-core causal flash attention (proven config, unchanged).
// CTA: 256 threads (8 warps), Q tile 128 rows (16/warp), kv tile 64.
// exp2-domain softmax with f16x2 MUFU; row sums via ones-MMA; cp.async
// double-buffered K/V (.cg fills). smem 54KB dynamic -> 2 CTAs/SM.
// ---------------------------------------------------------------------------
#define AST 72
#define ATTN_SMEM ((128*AST + 4*64*AST) * 2)
#define ONES2 0x3C003C00u

__global__ __launch_bounds__(256, 2)
void attn_h(const __half* __restrict__ Qb, const __half* __restrict__ Kb,
            const __half* __restrict__ Vb, __half* __restrict__ Ob)
{
    extern __shared__ __half dsm[];
    __half* Qsm = dsm;                         // [128][AST]
    __half* Ksm = dsm + 128 * AST;             // [2][64][AST]
    __half* Vsm = dsm + 128 * AST + 2 * 64 * AST;

    const int qt = (int)gridDim.x - 1 - (int)blockIdx.x;   // long rows first
    const int h = blockIdx.y, b = blockIdx.z;
    const int tid = threadIdx.x, wid = tid >> 5, lane = tid & 31;
    const int lg = lane >> 2, la3 = lane & 3;
    const int wb = wid * 16;
    const float NEG_INF = __int_as_float(0xff800000);

    const size_t base = (size_t)b * SEQ * DM + (size_t)h * HD;
    const int sr = tid >> 3, sc = (tid & 7) * 8;
    const unsigned SOFF = 64 * AST * 2;

    {
        const __half* Kg = Kb + base;
        const __half* Vg = Vb + base;
        #pragma unroll
        for (int p = 0; p < 2; p++) {
            const int r = sr + p * 32;
            cpa16(su32(Ksm + r * AST + sc), Kg + (size_t)r * DM + sc);
            cpa16(su32(Vsm + r * AST + sc), Vg + (size_t)r * DM + sc);
        }
        cpa_commit();
    }

    {
        const __half* Qg = Qb + base + (size_t)(qt * 128) * DM;
        #pragma unroll
        for (int p = 0; p < 4; p++) {
            const int r = sr + p * 32;
            *(uint4*)(Qsm + r * AST + sc) = *(const uint4*)(Qg + (size_t)r * DM + sc);
        }
    }
    __syncthreads();
    unsigned Qf[4][4];
    {
        unsigned qaddr = su32(Qsm + (wb + (lane & 15)) * AST + (lane >> 4) * 8);
        #pragma unroll
        for (int k16 = 0; k16 < 4; k16++)
            ldsm4(Qf[k16][0], Qf[k16][1], Qf[k16][2], Qf[k16][3],
                  qaddr + k16 * 32);
    }

    const unsigned kbase = su32(Ksm) +
        ((lane & 7) + ((lane >> 4) << 3)) * (AST * 2) + (lane & 8) * 2;
    const unsigned vbase = su32(Vsm) +
        (lane & 15) * (AST * 2) + (lane >> 4) * 16;

    float m0 = NEG_INF, m1 = NEG_INF, l0 = 0.f, l1 = 0.f;
    float O[8][4];
    #pragma unroll
    for (int nt = 0; nt < 8; nt++)
        #pragma unroll
        for (int i = 0; i < 4; i++) O[nt][i] = 0.f;

    const int ntiles = 2 * qt + 2;
    for (int kt = 0; kt < ntiles; kt++) {
        const int cur = kt & 1;
        cpa_wait0();
        __syncthreads();

        if (kt + 1 < ntiles) {
            const __half* Kg = Kb + base + (size_t)((kt + 1) * 64) * DM;
            const __half* Vg = Vb + base + (size_t)((kt + 1) * 64) * DM;
            const int s = cur ^ 1;
            #pragma unroll
            for (int p = 0; p < 2; p++) {
                const int r = sr + p * 32;
                cpa16(su32(Ksm) + s * SOFF + (r * AST + sc) * 2,
                      Kg + (size_t)r * DM + sc);
                cpa16(su32(Vsm) + s * SOFF + (r * AST + sc) * 2,
                      Vg + (size_t)r * DM + sc);
            }
            cpa_commit();
        }

        const unsigned kaddr = kbase + cur * SOFF;
        const unsigned vaddr = vbase + cur * SOFF;

        float S[8][4];
        #pragma unroll
        for (int nt = 0; nt < 8; nt++)
            #pragma unroll
            for (int i = 0; i < 4; i++) S[nt][i] = 0.f;

        #pragma unroll
        for (int k16 = 0; k16 < 4; k16++)
            #pragma unroll
            for (int n16 = 0; n16 < 4; n16++) {
                unsigned r0, r1, r2, r3;
                ldsm4(r0, r1, r2, r3,
                      kaddr + n16 * 16 * (AST * 2) + k16 * 32);
                mma16(S[2 * n16    ], Qf[k16], r0, r1);
                mma16(S[2 * n16 + 1], Qf[k16], r2, r3);
            }

        if (kt >= 2 * qt) {
            const int rg0 = qt * 128 + wb + lg, rg1 = rg0 + 8;
            #pragma unroll
            for (int nt = 0; nt < 8; nt++) {
                const int cg = kt * 64 + nt * 8 + 2 * la3;
                if (cg     > rg0) S[nt][0] = NEG_INF;
                if (cg + 1 > rg0) S[nt][1] = NEG_INF;
                if (cg     > rg1) S[nt][2] = NEG_INF;
                if (cg + 1 > rg1) S[nt][3] = NEG_INF;
            }
        }

        float mx0 = NEG_INF, mx1 = NEG_INF;
        #pragma unroll
        for (int nt = 0; nt < 8; nt++) {
            mx0 = fmaxf(mx0, fmaxf(S[nt][0], S[nt][1]));
            mx1 = fmaxf(mx1, fmaxf(S[nt][2], S[nt][3]));
        }
        mx0 = fmaxf(mx0, __shfl_xor_sync(0xffffffffu, mx0, 1));
        mx0 = fmaxf(mx0, __shfl_xor_sync(0xffffffffu, mx0, 2));
        mx1 = fmaxf(mx1, __shfl_xor_sync(0xffffffffu, mx1, 1));
        mx1 = fmaxf(mx1, __shfl_xor_sync(0xffffffffu, mx1, 2));
        const float mn0 = fmaxf(m0, mx0), mn1 = fmaxf(m1, mx1);
        const float al0 = ex2f(m0 - mn0), al1 = ex2f(m1 - mn1);
        m0 = mn0;  m1 = mn1;

        unsigned Pf[4][4];
        #pragma unroll
        for (int k16 = 0; k16 < 4; k16++) {
            Pf[k16][0] = hex2(pack2(S[2*k16  ][0] - mn0, S[2*k16  ][1] - mn0));
            Pf[k16][1] = hex2(pack2(S[2*k16  ][2] - mn1, S[2*k16  ][3] - mn1));
            Pf[k16][2] = hex2(pack2(S[2*k16+1][0] - mn0, S[2*k16+1][1] - mn0));
            Pf[k16][3] = hex2(pack2(S[2*k16+1][2] - mn1, S[2*k16+1][3] - mn1));
        }

        float ssum[4] = {0.f, 0.f, 0.f, 0.f};
        #pragma unroll
        for (int k16 = 0; k16 < 4; k16++)
            mma16(ssum, Pf[k16], ONES2, ONES2);
        l0 = l0 * al0 + ssum[0];
        l1 = l1 * al1 + ssum[2];

        #pragma unroll
        for (int nt = 0; nt < 8; nt++) {
            O[nt][0] *= al0;  O[nt][1] *= al0;
            O[nt][2] *= al1;  O[nt][3] *= al1;
        }

        #pragma unroll
        for (int k16 = 0; k16 < 4; k16++)
            #pragma unroll
            for (int n16 = 0; n16 < 4; n16++) {
                unsigned r0, r1, r2, r3;
                ldsm4t(r0, r1, r2, r3,
                       vaddr + k16 * 16 * (AST * 2) + n16 * 32);
                mma16(O[2 * n16    ], Pf[k16], r0, r1);
                mma16(O[2 * n16 + 1], Pf[k16], r2, r3);
            }
    }

    __half* Og = Ob + base + (size_t)(qt * 128) * DM;
    const float il0 = 1.0f / l0, il1 = 1.0f / l1;
    const int r0 = wb + lg, r1 = r0 + 8;
    #pragma unroll
    for (int nt = 0; nt < 8; nt++) {
        const int col = nt * 8 + 2 * la3;
        *(unsigned*)&Og[(size_t)r0 * DM + col] =
            pack2(O[nt][0] * il0, O[nt][1] * il0);
        *(unsigned*)&Og[(size_t)r1 * DM + col] =
            pack2(O[nt][2] * il1, O[nt][3] * il1);
    }
}

// ---------------------------------------------------------------------------
extern "C" void kernel_launch(void* const* d_in, const int* in_sizes, int n_in,
                              void* d_out, int out_size)
{
    const float* x  = (const float*)d_in[0];
    const float* Ww = (const float*)d_in[1];
    const float* Wb = (const float*)d_in[2];
    const float* Ow = (const float*)d_in[3];
    const float* Ob = (const float*)d_in[4];
    float* out = (float*)d_out;

    __half *q, *k, *v, *c1, *c2, *xh, *wh, *oh;
    cudaGetSymbolAddress((void**)&q,  g_q);
    cudaGetSymbolAddress((void**)&k,  g_k);
    cudaGetSymbolAddress((void**)&v,  g_v);
    cudaGetSymbolAddress((void**)&c1, g_c1);
    cudaGetSymbolAddress((void**)&c2, g_c2);
    cudaGetSymbolAddress((void**)&xh, g_xh);
    cudaGetSymbolAddress((void**)&wh, g_wh);
    cudaGetSymbolAddress((void**)&oh, g_oh);

    cudaFuncSetAttribute(attn_h,
                         cudaFuncAttributeMaxDynamicSharedMemorySize, ATTN_SMEM);
    cudaFuncSetAttribute(gemm_hh<0>,
                         cudaFuncAttributeMaxDynamicSharedMemorySize, GEMM_SMEM);
    cudaFuncSetAttribute(gemm_hh<1>,
                         cudaFuncAttributeMaxDynamicSharedMemorySize, GEMM_SMEM);

    // 0) one-time fp16 conversions
    f2h<<<(MROWS * DM) / 2048, 256>>>(x,  xh, MROWS * DM);
    f2h<<<(3 * DM * DM) / 2048, 256>>>(Ww, wh, 3 * DM * DM);
    f2h<<<(DM * DM) / 2048, 256>>>(Ow, oh, DM * DM);

    // 1) QKV projection + bias -> fp16 q/k/v (k pre-scaled by log2e/8)
    dim3 g1(3 * DM / 128, MROWS / 128);
    gemm_hh<1><<<g1, 256, GEMM_SMEM>>>(xh, wh, Wb, nullptr,
                                       MROWS, 3 * DM, DM, q, k, v);

    // 2-4) repeated causal attention (fp16 in/out)
    dim3 ga(SEQ / 128, NH, BATCH);
    attn_h<<<ga, 256, ATTN_SMEM>>>(q,  k, v, c1);
    attn_h<<<ga, 256, ATTN_SMEM>>>(c1, k, v, c2);
    attn_h<<<ga, 256, ATTN_SMEM>>>(c2, k, v, c1);

    // 5) output projection + bias (f32 out)
    dim3 g2(DM / 128, MROWS / 128);
    gemm_hh<0><<<g2, 256, GEMM_SMEM>>>(c1, oh, Ob, out, MROWS, DM, DM,
                                       nullptr, nullptr, nullptr);
}

// round 13
// speedup vs baseline: 1.6409x; 1.6409x over previous
#include <cuda_runtime.h>
#include <cuda_fp16.h>

#define DM    1024
#define NH    16
#define HD    64
#define BATCH 2
#define SEQ   2048
#define MROWS (BATCH*SEQ)      // 4096

// log2(e)/sqrt(64) folded into K: scores come out in log2 units
#define KSCALE 0.1803368801111137f

// Scratch (device globals, fp16 — no allocation allowed)
__device__ __half g_q  [MROWS*DM];
__device__ __half g_k  [MROWS*DM];
__device__ __half g_v  [MROWS*DM];
__device__ __half g_c1 [MROWS*DM];
__device__ __half g_c2 [MROWS*DM];
__device__ __half g_xh [MROWS*DM];       // x   -> fp16
__device__ __half g_wh [3*DM*DM];        // Wqkv -> fp16
__device__ __half g_oh [DM*DM];          // out_w -> fp16

__device__ __forceinline__ unsigned pack2(float a, float b) {
    __half2 h = __floats2half2_rn(a, b);
    return *(unsigned*)&h;
}
__device__ __forceinline__ unsigned su32(const void* p) {
    return (unsigned)__cvta_generic_to_shared(p);
}
__device__ __forceinline__ float ex2f(float x) {
    float r; asm("ex2.approx.f32 %0, %1;" : "=f"(r) : "f"(x)); return r;
}
__device__ __forceinline__ unsigned hex2(unsigned x) {
    unsigned r; asm("ex2.approx.f16x2 %0, %1;" : "=r"(r) : "r"(x)); return r;
}
__device__ __forceinline__ void mma16(float* d, const unsigned* a,
                                      unsigned b0, unsigned b1) {
    asm volatile(
        "mma.sync.aligned.m16n8k16.row.col.f32.f16.f16.f32 "
        "{%0,%1,%2,%3}, {%4,%5,%6,%7}, {%8,%9}, {%0,%1,%2,%3};"
        : "+f"(d[0]), "+f"(d[1]), "+f"(d[2]), "+f"(d[3])
        : "r"(a[0]), "r"(a[1]), "r"(a[2]), "r"(a[3]), "r"(b0), "r"(b1));
}
__device__ __forceinline__ void ldsm4(unsigned& r0, unsigned& r1,
                                      unsigned& r2, unsigned& r3, unsigned a) {
    asm volatile("ldmatrix.sync.aligned.m8n8.x4.shared.b16 {%0,%1,%2,%3}, [%4];"
        : "=r"(r0), "=r"(r1), "=r"(r2), "=r"(r3) : "r"(a));
}
__device__ __forceinline__ void ldsm4t(unsigned& r0, unsigned& r1,
                                       unsigned& r2, unsigned& r3, unsigned a) {
    asm volatile("ldmatrix.sync.aligned.m8n8.x4.trans.shared.b16 {%0,%1,%2,%3}, [%4];"
        : "=r"(r0), "=r"(r1), "=r"(r2), "=r"(r3) : "r"(a));
}
// .cg: bypass L1 on the fill — tiles are stream-once, never re-read via L1
__device__ __forceinline__ void cpa16(unsigned dst, const void* src) {
    asm volatile("cp.async.cg.shared.global [%0], [%1], 16;"
        :: "r"(dst), "l"(src));
}
__device__ __forceinline__ void cpa_commit() {
    asm volatile("cp.async.commit_group;");
}
__device__ __forceinline__ void cpa_wait1() {
    asm volatile("cp.async.wait_group 1;" ::: "memory");
}
__device__ __forceinline__ void cpa_wait2() {
    asm volatile("cp.async.wait_group 2;" ::: "memory");
}

// ---------------------------------------------------------------------------
// f32 -> fp16 bulk convert (8 elems/thread)
// ---------------------------------------------------------------------------
__global__ __launch_bounds__(256)
void f2h(const float* __restrict__ in, __half* __restrict__ out, int n)
{
    int i = (blockIdx.x * 256 + threadIdx.x) * 8;
    if (i >= n) return;
    float4 a = *(const float4*)(in + i);
    float4 b = *(const float4*)(in + i + 4);
    *(uint4*)(out + i) = make_uint4(pack2(a.x, a.y), pack2(a.z, a.w),
                                    pack2(b.x, b.y), pack2(b.z, b.w));
}

// ---------------------------------------------------------------------------
// All-fp16 cp.async 4-stage pipelined GEMM: C[M,N] = A @ B^T + bias
// MODE 0: f32 write to C; MODE 1: qkv scatter to fp16 buffers (k * KSCALE)
// CTA 128x128, 256 threads (8 warps 4x2), warp tile 32x64, kc=32.
// (Round-11 proven config: 4 stages + .cg fills. Do not perturb.)
// ---------------------------------------------------------------------------
#define GST 40                         // half stride (32 + pad 8)
#define GSOF (128*GST*2)               // bytes per stage per matrix
#define GEMM_SMEM (2*4*128*GST*2)      // 82 KB (4 stages, A+B)

template<int MODE>
__global__ __launch_bounds__(256, 2)
void gemm_hh(const __half* __restrict__ A, const __half* __restrict__ B,
             const float* __restrict__ bias, float* __restrict__ C,
             int M, int N, int K,
             __half* __restrict__ qo, __half* __restrict__ ko,
             __half* __restrict__ vo)
{
    extern __shared__ __half gsm[];
    __half* As = gsm;                  // [4][128][GST]
    __half* Bs = gsm + 4 * 128 * GST;

    const int tid = threadIdx.x;
    const int wid = tid >> 5, lane = tid & 31;
    const int lg = lane >> 2, la3 = lane & 3;
    const int wm = wid & 3, wn = wid >> 2;          // warp grid 4x2
    const int bm = blockIdx.y * 128, bn = blockIdx.x * 128;

    float acc[2][8][4];
    #pragma unroll
    for (int mt = 0; mt < 2; mt++)
        #pragma unroll
        for (int nt = 0; nt < 8; nt++)
            #pragma unroll
            for (int i = 0; i < 4; i++) acc[mt][nt][i] = 0.f;

    const int lrow = tid >> 1, lcolh = (tid & 1) * 16;  // 128 rows x 32 halfs
    const __half* Ap = A + (size_t)(bm + lrow) * K + lcolh;
    const __half* Bp = B + (size_t)(bn + lrow) * K + lcolh;
    const unsigned adst = su32(As + lrow * GST + lcolh);
    const unsigned bdst = su32(Bs + lrow * GST + lcolh);

    // prologue: stages 0..2 (2 x 16B per matrix per thread per stage)
    #pragma unroll
    for (int st = 0; st < 3; st++) {
        const int k0 = 32 * st;
        cpa16(adst + st * GSOF,      Ap + k0);
        cpa16(adst + st * GSOF + 16, Ap + k0 + 8);
        cpa16(bdst + st * GSOF,      Bp + k0);
        cpa16(bdst + st * GSOF + 16, Bp + k0 + 8);
        cpa_commit();
    }

    const unsigned a_frag = su32(As + (wm * 32 + (lane & 15)) * GST + (lane >> 4) * 8);
    const unsigned b_frag = su32(Bs + (wn * 64 + ((lane & 7) + ((lane >> 4) << 3))) * GST)
                            + (lane & 8) * 2;

    const int NIT = K / 32;
    int s = 0;
    for (int it = 0; it < NIT; it++) {
        cpa_wait2();
        __syncthreads();
        const unsigned soff = s * GSOF;

        #pragma unroll
        for (int ks = 0; ks < 2; ks++) {
            unsigned af[2][4];
            #pragma unroll
            for (int mt = 0; mt < 2; mt++)
                ldsm4(af[mt][0], af[mt][1], af[mt][2], af[mt][3],
                      a_frag + soff + (mt * 16 * GST + ks * 16) * 2);
            #pragma unroll
            for (int n16 = 0; n16 < 4; n16++) {
                unsigned r0, r1, r2, r3;
                ldsm4(r0, r1, r2, r3,
                      b_frag + soff + (n16 * 16 * GST + ks * 16) * 2);
                #pragma unroll
                for (int mt = 0; mt < 2; mt++) {
                    mma16(acc[mt][2 * n16    ], af[mt], r0, r1);
                    mma16(acc[mt][2 * n16 + 1], af[mt], r2, r3);
                }
            }
        }

        if (it + 3 < NIT) {       // stream stage it+3 into slot (it+3)%4
            const int ns = (s + 3) & 3;
            const int k0 = 32 * (it + 3);
            cpa16(adst + ns * GSOF,      Ap + k0);
            cpa16(adst + ns * GSOF + 16, Ap + k0 + 8);
            cpa16(bdst + ns * GSOF,      Bp + k0);
            cpa16(bdst + ns * GSOF + 16, Bp + k0 + 8);
        }
        cpa_commit();
        s = (s + 1) & 3;
    }

    #pragma unroll
    for (int mt = 0; mt < 2; mt++)
        #pragma unroll
        for (int nt = 0; nt < 8; nt++) {
            const int row0 = bm + wm * 32 + mt * 16 + lg;
            const int col  = bn + wn * 64 + nt * 8 + 2 * la3;
            float v0 = acc[mt][nt][0] + bias[col];
            float v1 = acc[mt][nt][1] + bias[col + 1];
            float v2 = acc[mt][nt][2] + bias[col];
            float v3 = acc[mt][nt][3] + bias[col + 1];
            if (MODE == 0) {
                *(float2*)&C[(size_t)row0 * N + col]       = make_float2(v0, v1);
                *(float2*)&C[(size_t)(row0 + 8) * N + col] = make_float2(v2, v3);
            } else {
                const int g = col >> 10, rem = col & 1023;
                if (g == 1) { v0 *= KSCALE; v1 *= KSCALE; v2 *= KSCALE; v3 *= KSCALE; }
                __half* dst = (g == 0) ? qo : (g == 1) ? ko : vo;
                *(unsigned*)&dst[(size_t)row0 * DM + rem]       = pack2(v0, v1);
                *(unsigned*)&dst[(size_t)(row0 + 8) * DM + rem] = pack2(v2, v3);
            }
        }
}

// ---------------------------------------------------------------------------
// FP16 tensor-core causal flash attention.
// CTA: 256 threads (8 warps), Q tile 128 rows (16/warp), kv tile 64.
// exp2-domain softmax with f16x2 MUFU; row sums via ones-MMA.
// K/V now TRIPLE-buffered (wait_group 1): a full extra tile of fill-latency
// slack so the top-of-loop wait never blocks. smem 73.7KB -> 2 CTAs/SM.
// ---------------------------------------------------------------------------
#define AST 72
#define ATTN_SMEM ((128*AST + 6*64*AST) * 2)   // Qsm + 3 stages x (K+V)
#define ONES2 0x3C003C00u

__global__ __launch_bounds__(256, 2)
void attn_h(const __half* __restrict__ Qb, const __half* __restrict__ Kb,
            const __half* __restrict__ Vb, __half* __restrict__ Ob)
{
    extern __shared__ __half dsm[];
    __half* Qsm = dsm;                         // [128][AST]
    __half* Ksm = dsm + 128 * AST;             // [3][64][AST]
    __half* Vsm = dsm + 128 * AST + 3 * 64 * AST;

    const int qt = (int)gridDim.x - 1 - (int)blockIdx.x;   // long rows first
    const int h = blockIdx.y, b = blockIdx.z;
    const int tid = threadIdx.x, wid = tid >> 5, lane = tid & 31;
    const int lg = lane >> 2, la3 = lane & 3;
    const int wb = wid * 16;
    const float NEG_INF = __int_as_float(0xff800000);

    const size_t base = (size_t)b * SEQ * DM + (size_t)h * HD;
    const int sr = tid >> 3, sc = (tid & 7) * 8;
    const unsigned SOFF = 64 * AST * 2;
    const int ntiles = 2 * qt + 2;             // >= 2 always

    // ---- prologue: issue cp.async for kv tiles 0 and 1 ----
    #pragma unroll
    for (int t0 = 0; t0 < 2; t0++) {
        const __half* Kg = Kb + base + (size_t)(t0 * 64) * DM;
        const __half* Vg = Vb + base + (size_t)(t0 * 64) * DM;
        #pragma unroll
        for (int p = 0; p < 2; p++) {
            const int r = sr + p * 32;
            cpa16(su32(Ksm) + t0 * SOFF + (r * AST + sc) * 2,
                  Kg + (size_t)r * DM + sc);
            cpa16(su32(Vsm) + t0 * SOFF + (r * AST + sc) * 2,
                  Vg + (size_t)r * DM + sc);
        }
        cpa_commit();
    }

    // ---- stage Q tile, then register-resident Q fragments ----
    {
        const __half* Qg = Qb + base + (size_t)(qt * 128) * DM;
        #pragma unroll
        for (int p = 0; p < 4; p++) {
            const int r = sr + p * 32;
            *(uint4*)(Qsm + r * AST + sc) = *(const uint4*)(Qg + (size_t)r * DM + sc);
        }
    }
    __syncthreads();
    unsigned Qf[4][4];
    {
        unsigned qaddr = su32(Qsm + (wb + (lane & 15)) * AST + (lane >> 4) * 8);
        #pragma unroll
        for (int k16 = 0; k16 < 4; k16++)
            ldsm4(Qf[k16][0], Qf[k16][1], Qf[k16][2], Qf[k16][3],
                  qaddr + k16 * 32);
    }

    const unsigned kbase = su32(Ksm) +
        ((lane & 7) + ((lane >> 4) << 3)) * (AST * 2) + (lane & 8) * 2;
    const unsigned vbase = su32(Vsm) +
        (lane & 15) * (AST * 2) + (lane >> 4) * 16;

    float m0 = NEG_INF, m1 = NEG_INF, l0 = 0.f, l1 = 0.f;
    float O[8][4];
    #pragma unroll
    for (int nt = 0; nt < 8; nt++)
        #pragma unroll
        for (int i = 0; i < 4; i++) O[nt][i] = 0.f;

    int cur = 0;
    for (int kt = 0; kt < ntiles; kt++) {
        cpa_wait1();                 // tile kt complete (kt+1 may be pending)
        __syncthreads();

        // prefetch kv tile kt+2 into stage (kt+2)%3 (read last at kt-1)
        if (kt + 2 < ntiles) {
            const __half* Kg = Kb + base + (size_t)((kt + 2) * 64) * DM;
            const __half* Vg = Vb + base + (size_t)((kt + 2) * 64) * DM;
            int ns = cur + 2; if (ns >= 3) ns -= 3;
            #pragma unroll
            for (int p = 0; p < 2; p++) {
                const int r = sr + p * 32;
                cpa16(su32(Ksm) + ns * SOFF + (r * AST + sc) * 2,
                      Kg + (size_t)r * DM + sc);
                cpa16(su32(Vsm) + ns * SOFF + (r * AST + sc) * 2,
                      Vg + (size_t)r * DM + sc);
            }
        }
        cpa_commit();

        const unsigned kaddr = kbase + cur * SOFF;
        const unsigned vaddr = vbase + cur * SOFF;

        float S[8][4];
        #pragma unroll
        for (int nt = 0; nt < 8; nt++)
            #pragma unroll
            for (int i = 0; i < 4; i++) S[nt][i] = 0.f;

        #pragma unroll
        for (int k16 = 0; k16 < 4; k16++)
            #pragma unroll
            for (int n16 = 0; n16 < 4; n16++) {
                unsigned r0, r1, r2, r3;
                ldsm4(r0, r1, r2, r3,
                      kaddr + n16 * 16 * (AST * 2) + k16 * 32);
                mma16(S[2 * n16    ], Qf[k16], r0, r1);
                mma16(S[2 * n16 + 1], Qf[k16], r2, r3);
            }

        if (kt >= 2 * qt) {
            const int rg0 = qt * 128 + wb + lg, rg1 = rg0 + 8;
            #pragma unroll
            for (int nt = 0; nt < 8; nt++) {
                const int cg = kt * 64 + nt * 8 + 2 * la3;
                if (cg     > rg0) S[nt][0] = NEG_INF;
                if (cg + 1 > rg0) S[nt][1] = NEG_INF;
                if (cg     > rg1) S[nt][2] = NEG_INF;
                if (cg + 1 > rg1) S[nt][3] = NEG_INF;
            }
        }

        float mx0 = NEG_INF, mx1 = NEG_INF;
        #pragma unroll
        for (int nt = 0; nt < 8; nt++) {
            mx0 = fmaxf(mx0, fmaxf(S[nt][0], S[nt][1]));
            mx1 = fmaxf(mx1, fmaxf(S[nt][2], S[nt][3]));
        }
        mx0 = fmaxf(mx0, __shfl_xor_sync(0xffffffffu, mx0, 1));
        mx0 = fmaxf(mx0, __shfl_xor_sync(0xffffffffu, mx0, 2));
        mx1 = fmaxf(mx1, __shfl_xor_sync(0xffffffffu, mx1, 1));
        mx1 = fmaxf(mx1, __shfl_xor_sync(0xffffffffu, mx1, 2));
        const float mn0 = fmaxf(m0, mx0), mn1 = fmaxf(m1, mx1);
        const float al0 = ex2f(m0 - mn0), al1 = ex2f(m1 - mn1);
        m0 = mn0;  m1 = mn1;

        unsigned Pf[4][4];
        #pragma unroll
        for (int k16 = 0; k16 < 4; k16++) {
            Pf[k16][0] = hex2(pack2(S[2*k16  ][0] - mn0, S[2*k16  ][1] - mn0));
            Pf[k16][1] = hex2(pack2(S[2*k16  ][2] - mn1, S[2*k16  ][3] - mn1));
            Pf[k16][2] = hex2(pack2(S[2*k16+1][0] - mn0, S[2*k16+1][1] - mn0));
            Pf[k16][3] = hex2(pack2(S[2*k16+1][2] - mn1, S[2*k16+1][3] - mn1));
        }

        float ssum[4] = {0.f, 0.f, 0.f, 0.f};
        #pragma unroll
        for (int k16 = 0; k16 < 4; k16++)
            mma16(ssum, Pf[k16], ONES2, ONES2);
        l0 = l0 * al0 + ssum[0];
        l1 = l1 * al1 + ssum[2];

        #pragma unroll
        for (int nt = 0; nt < 8; nt++) {
            O[nt][0] *= al0;  O[nt][1] *= al0;
            O[nt][2] *= al1;  O[nt][3] *= al1;
        }

        #pragma unroll
        for (int k16 = 0; k16 < 4; k16++)
            #pragma unroll
            for (int n16 = 0; n16 < 4; n16++) {
                unsigned r0, r1, r2, r3;
                ldsm4t(r0, r1, r2, r3,
                       vaddr + k16 * 16 * (AST * 2) + n16 * 32);
                mma16(O[2 * n16    ], Pf[k16], r0, r1);
                mma16(O[2 * n16 + 1], Pf[k16], r2, r3);
            }

        if (++cur == 3) cur = 0;
    }

    __half* Og = Ob + base + (size_t)(qt * 128) * DM;
    const float il0 = 1.0f / l0, il1 = 1.0f / l1;
    const int r0 = wb + lg, r1 = r0 + 8;
    #pragma unroll
    for (int nt = 0; nt < 8; nt++) {
        const int col = nt * 8 + 2 * la3;
        *(unsigned*)&Og[(size_t)r0 * DM + col] =
            pack2(O[nt][0] * il0, O[nt][1] * il0);
        *(unsigned*)&Og[(size_t)r1 * DM + col] =
            pack2(O[nt][2] * il1, O[nt][3] * il1);
    }
}

// ---------------------------------------------------------------------------
extern "C" void kernel_launch(void* const* d_in, const int* in_sizes, int n_in,
                              void* d_out, int out_size)
{
    const float* x  = (const float*)d_in[0];
    const float* Ww = (const float*)d_in[1];
    const float* Wb = (const float*)d_in[2];
    const float* Ow = (const float*)d_in[3];
    const float* Ob = (const float*)d_in[4];
    float* out = (float*)d_out;

    __half *q, *k, *v, *c1, *c2, *xh, *wh, *oh;
    cudaGetSymbolAddress((void**)&q,  g_q);
    cudaGetSymbolAddress((void**)&k,  g_k);
    cudaGetSymbolAddress((void**)&v,  g_v);
    cudaGetSymbolAddress((void**)&c1, g_c1);
    cudaGetSymbolAddress((void**)&c2, g_c2);
    cudaGetSymbolAddress((void**)&xh, g_xh);
    cudaGetSymbolAddress((void**)&wh, g_wh);
    cudaGetSymbolAddress((void**)&oh, g_oh);

    cudaFuncSetAttribute(attn_h,
                         cudaFuncAttributeMaxDynamicSharedMemorySize, ATTN_SMEM);
    cudaFuncSetAttribute(gemm_hh<0>,
                         cudaFuncAttributeMaxDynamicSharedMemorySize, GEMM_SMEM);
    cudaFuncSetAttribute(gemm_hh<1>,
                         cudaFuncAttributeMaxDynamicSharedMemorySize, GEMM_SMEM);

    // 0) one-time fp16 conversions
    f2h<<<(MROWS * DM) / 2048, 256>>>(x,  xh, MROWS * DM);
    f2h<<<(3 * DM * DM) / 2048, 256>>>(Ww, wh, 3 * DM * DM);
    f2h<<<(DM * DM) / 2048, 256>>>(Ow, oh, DM * DM);

    // 1) QKV projection + bias -> fp16 q/k/v (k pre-scaled by log2e/8)
    dim3 g1(3 * DM / 128, MROWS / 128);
    gemm_hh<1><<<g1, 256, GEMM_SMEM>>>(xh, wh, Wb, nullptr,
                                       MROWS, 3 * DM, DM, q, k, v);

    // 2-4) repeated causal attention (fp16 in/out)
    dim3 ga(SEQ / 128, NH, BATCH);
    attn_h<<<ga, 256, ATTN_SMEM>>>(q,  k, v, c1);
    attn_h<<<ga, 256, ATTN_SMEM>>>(c1, k, v, c2);
    attn_h<<<ga, 256, ATTN_SMEM>>>(c2, k, v, c1);

    // 5) output projection + bias (f32 out)
    dim3 g2(DM / 128, MROWS / 128);
    gemm_hh<0><<<g2, 256, GEMM_SMEM>>>(c1, oh, Ob, out, MROWS, DM, DM,
                                       nullptr, nullptr, nullptr);
}

// round 17
// speedup vs baseline: 1.6684x; 1.0168x over previous
#include <cuda_runtime.h>
#include <cuda_fp16.h>

#define DM    1024
#define NH    16
#define HD    64
#define BATCH 2
#define SEQ   2048
#define MROWS (BATCH*SEQ)      // 4096

// log2(e)/sqrt(64) folded into K: scores come out in log2 units
#define KSCALE 0.1803368801111137f

// Scratch (device globals, fp16 — no allocation allowed)
__device__ __half g_q  [MROWS*DM];
__device__ __half g_k  [MROWS*DM];
__device__ __half g_v  [MROWS*DM];
__device__ __half g_c1 [MROWS*DM];
__device__ __half g_c2 [MROWS*DM];
__device__ __half g_xh [MROWS*DM];       // x   -> fp16
__device__ __half g_wh [3*DM*DM];        // Wqkv -> fp16
__device__ __half g_oh [DM*DM];          // out_w -> fp16

__device__ __forceinline__ unsigned pack2(float a, float b) {
    __half2 h = __floats2half2_rn(a, b);
    return *(unsigned*)&h;
}
__device__ __forceinline__ unsigned su32(const void* p) {
    return (unsigned)__cvta_generic_to_shared(p);
}
__device__ __forceinline__ float ex2f(float x) {
    float r; asm("ex2.approx.f32 %0, %1;" : "=f"(r) : "f"(x)); return r;
}
__device__ __forceinline__ unsigned hex2(unsigned x) {
    unsigned r; asm("ex2.approx.f16x2 %0, %1;" : "=r"(r) : "r"(x)); return r;
}
__device__ __forceinline__ void mma16(float* d, const unsigned* a,
                                      unsigned b0, unsigned b1) {
    asm volatile(
        "mma.sync.aligned.m16n8k16.row.col.f32.f16.f16.f32 "
        "{%0,%1,%2,%3}, {%4,%5,%6,%7}, {%8,%9}, {%0,%1,%2,%3};"
        : "+f"(d[0]), "+f"(d[1]), "+f"(d[2]), "+f"(d[3])
        : "r"(a[0]), "r"(a[1]), "r"(a[2]), "r"(a[3]), "r"(b0), "r"(b1));
}
__device__ __forceinline__ void ldsm4(unsigned& r0, unsigned& r1,
                                      unsigned& r2, unsigned& r3, unsigned a) {
    asm volatile("ldmatrix.sync.aligned.m8n8.x4.shared.b16 {%0,%1,%2,%3}, [%4];"
        : "=r"(r0), "=r"(r1), "=r"(r2), "=r"(r3) : "r"(a));
}
__device__ __forceinline__ void ldsm4t(unsigned& r0, unsigned& r1,
                                       unsigned& r2, unsigned& r3, unsigned a) {
    asm volatile("ldmatrix.sync.aligned.m8n8.x4.trans.shared.b16 {%0,%1,%2,%3}, [%4];"
        : "=r"(r0), "=r"(r1), "=r"(r2), "=r"(r3) : "r"(a));
}
// .cg: bypass L1 on the fill — tiles are stream-once, never re-read via L1
__device__ __forceinline__ void cpa16(unsigned dst, const void* src) {
    asm volatile("cp.async.cg.shared.global [%0], [%1], 16;"
        :: "r"(dst), "l"(src));
}
__device__ __forceinline__ void cpa_commit() {
    asm volatile("cp.async.commit_group;");
}
__device__ __forceinline__ void cpa_wait1() {
    asm volatile("cp.async.wait_group 1;" ::: "memory");
}
__device__ __forceinline__ void cpa_wait2() {
    asm volatile("cp.async.wait_group 2;" ::: "memory");
}

// ---------------------------------------------------------------------------
// f32 -> fp16 bulk convert, all three tensors in ONE launch (8 elems/thread)
// ---------------------------------------------------------------------------
#define N_X  (MROWS*DM)        // 4M
#define N_W  (3*DM*DM)         // 3M
#define N_O  (DM*DM)           // 1M

__global__ __launch_bounds__(256)
void f2h3(const float* __restrict__ x,  __half* __restrict__ xh,
          const float* __restrict__ w,  __half* __restrict__ wh,
          const float* __restrict__ o,  __half* __restrict__ oh)
{
    int i = (blockIdx.x * 256 + threadIdx.x) * 8;
    const float* in; __half* out;
    if (i < N_X)            { in = x + i;               out = xh + i; }
    else if (i < N_X + N_W) { in = w + (i - N_X);       out = wh + (i - N_X); }
    else if (i < N_X + N_W + N_O)
                            { in = o + (i - N_X - N_W); out = oh + (i - N_X - N_W); }
    else return;
    float4 a = *(const float4*)(in);
    float4 b = *(const float4*)(in + 4);
    *(uint4*)(out) = make_uint4(pack2(a.x, a.y), pack2(a.z, a.w),
                                pack2(b.x, b.y), pack2(b.z, b.w));
}

// ---------------------------------------------------------------------------
// All-fp16 cp.async 4-stage pipelined GEMM: C[M,N] = A @ B^T + bias
// MODE 0: f32 write to C; MODE 1: qkv scatter to fp16 buffers (k * KSCALE)
// CTA 128x128, 256 threads (8 warps 4x2), warp tile 32x64, kc=32.
// (Proven 392us config: 4 stages + .cg fills. Do not perturb.)
// ---------------------------------------------------------------------------
#define GST 40                         // half stride (32 + pad 8)
#define GSOF (128*GST*2)               // bytes per stage per matrix
#define GEMM_SMEM (2*4*128*GST*2)      // 82 KB (4 stages, A+B)

template<int MODE>
__global__ __launch_bounds__(256, 2)
void gemm_hh(const __half* __restrict__ A, const __half* __restrict__ B,
             const float* __restrict__ bias, float* __restrict__ C,
             int M, int N, int K,
             __half* __restrict__ qo, __half* __restrict__ ko,
             __half* __restrict__ vo)
{
    extern __shared__ __half gsm[];
    __half* As = gsm;                  // [4][128][GST]
    __half* Bs = gsm + 4 * 128 * GST;

    const int tid = threadIdx.x;
    const int wid = tid >> 5, lane = tid & 31;
    const int lg = lane >> 2, la3 = lane & 3;
    const int wm = wid & 3, wn = wid >> 2;          // warp grid 4x2
    const int bm = blockIdx.y * 128, bn = blockIdx.x * 128;

    float acc[2][8][4];
    #pragma unroll
    for (int mt = 0; mt < 2; mt++)
        #pragma unroll
        for (int nt = 0; nt < 8; nt++)
            #pragma unroll
            for (int i = 0; i < 4; i++) acc[mt][nt][i] = 0.f;

    const int lrow = tid >> 1, lcolh = (tid & 1) * 16;  // 128 rows x 32 halfs
    const __half* Ap = A + (size_t)(bm + lrow) * K + lcolh;
    const __half* Bp = B + (size_t)(bn + lrow) * K + lcolh;
    const unsigned adst = su32(As + lrow * GST + lcolh);
    const unsigned bdst = su32(Bs + lrow * GST + lcolh);

    // prologue: stages 0..2 (2 x 16B per matrix per thread per stage)
    #pragma unroll
    for (int st = 0; st < 3; st++) {
        const int k0 = 32 * st;
        cpa16(adst + st * GSOF,      Ap + k0);
        cpa16(adst + st * GSOF + 16, Ap + k0 + 8);
        cpa16(bdst + st * GSOF,      Bp + k0);
        cpa16(bdst + st * GSOF + 16, Bp + k0 + 8);
        cpa_commit();
    }

    const unsigned a_frag = su32(As + (wm * 32 + (lane & 15)) * GST + (lane >> 4) * 8);
    const unsigned b_frag = su32(Bs + (wn * 64 + ((lane & 7) + ((lane >> 4) << 3))) * GST)
                            + (lane & 8) * 2;

    const int NIT = K / 32;
    int s = 0;
    for (int it = 0; it < NIT; it++) {
        cpa_wait2();
        __syncthreads();
        const unsigned soff = s * GSOF;

        #pragma unroll
        for (int ks = 0; ks < 2; ks++) {
            unsigned af[2][4];
            #pragma unroll
            for (int mt = 0; mt < 2; mt++)
                ldsm4(af[mt][0], af[mt][1], af[mt][2], af[mt][3],
                      a_frag + soff + (mt * 16 * GST + ks * 16) * 2);
            #pragma unroll
            for (int n16 = 0; n16 < 4; n16++) {
                unsigned r0, r1, r2, r3;
                ldsm4(r0, r1, r2, r3,
                      b_frag + soff + (n16 * 16 * GST + ks * 16) * 2);
                #pragma unroll
                for (int mt = 0; mt < 2; mt++) {
                    mma16(acc[mt][2 * n16    ], af[mt], r0, r1);
                    mma16(acc[mt][2 * n16 + 1], af[mt], r2, r3);
                }
            }
        }

        if (it + 3 < NIT) {       // stream stage it+3 into slot (it+3)%4
            const int ns = (s + 3) & 3;
            const int k0 = 32 * (it + 3);
            cpa16(adst + ns * GSOF,      Ap + k0);
            cpa16(adst + ns * GSOF + 16, Ap + k0 + 8);
            cpa16(bdst + ns * GSOF,      Bp + k0);
            cpa16(bdst + ns * GSOF + 16, Bp + k0 + 8);
        }
        cpa_commit();
        s = (s + 1) & 3;
    }

    #pragma unroll
    for (int mt = 0; mt < 2; mt++)
        #pragma unroll
        for (int nt = 0; nt < 8; nt++) {
            const int row0 = bm + wm * 32 + mt * 16 + lg;
            const int col  = bn + wn * 64 + nt * 8 + 2 * la3;
            float v0 = acc[mt][nt][0] + bias[col];
            float v1 = acc[mt][nt][1] + bias[col + 1];
            float v2 = acc[mt][nt][2] + bias[col];
            float v3 = acc[mt][nt][3] + bias[col + 1];
            if (MODE == 0) {
                *(float2*)&C[(size_t)row0 * N + col]       = make_float2(v0, v1);
                *(float2*)&C[(size_t)(row0 + 8) * N + col] = make_float2(v2, v3);
            } else {
                const int g = col >> 10, rem = col & 1023;
                if (g == 1) { v0 *= KSCALE; v1 *= KSCALE; v2 *= KSCALE; v3 *= KSCALE; }
                __half* dst = (g == 0) ? qo : (g == 1) ? ko : vo;
                *(unsigned*)&dst[(size_t)row0 * DM + rem]       = pack2(v0, v1);
                *(unsigned*)&dst[(size_t)(row0 + 8) * DM + rem] = pack2(v2, v3);
            }
        }
}

// ---------------------------------------------------------------------------
// FP16 tensor-core causal flash attention (proven 392us config, unchanged).
// CTA: 256 threads (8 warps), Q tile 128 rows (16/warp), kv tile 64.
// exp2-domain softmax with f16x2 MUFU; row sums via ones-MMA.
// K/V triple-buffered (wait_group 1). smem 73.7KB -> 2 CTAs/SM.
// ---------------------------------------------------------------------------
#define AST 72
#define ATTN_SMEM ((128*AST + 6*64*AST) * 2)   // Qsm + 3 stages x (K+V)
#define ONES2 0x3C003C00u

__global__ __launch_bounds__(256, 2)
void attn_h(const __half* __restrict__ Qb, const __half* __restrict__ Kb,
            const __half* __restrict__ Vb, __half* __restrict__ Ob)
{
    extern __shared__ __half dsm[];
    __half* Qsm = dsm;                         // [128][AST]
    __half* Ksm = dsm + 128 * AST;             // [3][64][AST]
    __half* Vsm = dsm + 128 * AST + 3 * 64 * AST;

    const int qt = (int)gridDim.x - 1 - (int)blockIdx.x;   // long rows first
    const int h = blockIdx.y, b = blockIdx.z;
    const int tid = threadIdx.x, wid = tid >> 5, lane = tid & 31;
    const int lg = lane >> 2, la3 = lane & 3;
    const int wb = wid * 16;
    const float NEG_INF = __int_as_float(0xff800000);

    const size_t base = (size_t)b * SEQ * DM + (size_t)h * HD;
    const int sr = tid >> 3, sc = (tid & 7) * 8;
    const unsigned SOFF = 64 * AST * 2;
    const int ntiles = 2 * qt + 2;             // >= 2 always

    // ---- prologue: issue cp.async for kv tiles 0 and 1 ----
    #pragma unroll
    for (int t0 = 0; t0 < 2; t0++) {
        const __half* Kg = Kb + base + (size_t)(t0 * 64) * DM;
        const __half* Vg = Vb + base + (size_t)(t0 * 64) * DM;
        #pragma unroll
        for (int p = 0; p < 2; p++) {
            const int r = sr + p * 32;
            cpa16(su32(Ksm) + t0 * SOFF + (r * AST + sc) * 2,
                  Kg + (size_t)r * DM + sc);
            cpa16(su32(Vsm) + t0 * SOFF + (r * AST + sc) * 2,
                  Vg + (size_t)r * DM + sc);
        }
        cpa_commit();
    }

    // ---- stage Q tile, then register-resident Q fragments ----
    {
        const __half* Qg = Qb + base + (size_t)(qt * 128) * DM;
        #pragma unroll
        for (int p = 0; p < 4; p++) {
            const int r = sr + p * 32;
            *(uint4*)(Qsm + r * AST + sc) = *(const uint4*)(Qg + (size_t)r * DM + sc);
        }
    }
    __syncthreads();
    unsigned Qf[4][4];
    {
        unsigned qaddr = su32(Qsm + (wb + (lane & 15)) * AST + (lane >> 4) * 8);
        #pragma unroll
        for (int k16 = 0; k16 < 4; k16++)
            ldsm4(Qf[k16][0], Qf[k16][1], Qf[k16][2], Qf[k16][3],
                  qaddr + k16 * 32);
    }

    const unsigned kbase = su32(Ksm) +
        ((lane & 7) + ((lane >> 4) << 3)) * (AST * 2) + (lane & 8) * 2;
    const unsigned vbase = su32(Vsm) +
        (lane & 15) * (AST * 2) + (lane >> 4) * 16;

    float m0 = NEG_INF, m1 = NEG_INF, l0 = 0.f, l1 = 0.f;
    float O[8][4];
    #pragma unroll
    for (int nt = 0; nt < 8; nt++)
        #pragma unroll
        for (int i = 0; i < 4; i++) O[nt][i] = 0.f;

    int cur = 0;
    for (int kt = 0; kt < ntiles; kt++) {
        cpa_wait1();                 // tile kt complete (kt+1 may be pending)
        __syncthreads();

        // prefetch kv tile kt+2 into stage (kt+2)%3 (read last at kt-1)
        if (kt + 2 < ntiles) {
            const __half* Kg = Kb + base + (size_t)((kt + 2) * 64) * DM;
            const __half* Vg = Vb + base + (size_t)((kt + 2) * 64) * DM;
            int ns = cur + 2; if (ns >= 3) ns -= 3;
            #pragma unroll
            for (int p = 0; p < 2; p++) {
                const int r = sr + p * 32;
                cpa16(su32(Ksm) + ns * SOFF + (r * AST + sc) * 2,
                      Kg + (size_t)r * DM + sc);
                cpa16(su32(Vsm) + ns * SOFF + (r * AST + sc) * 2,
                      Vg + (size_t)r * DM + sc);
            }
        }
        cpa_commit();

        const unsigned kaddr = kbase + cur * SOFF;
        const unsigned vaddr = vbase + cur * SOFF;

        float S[8][4];
        #pragma unroll
        for (int nt = 0; nt < 8; nt++)
            #pragma unroll
            for (int i = 0; i < 4; i++) S[nt][i] = 0.f;

        #pragma unroll
        for (int k16 = 0; k16 < 4; k16++)
            #pragma unroll
            for (int n16 = 0; n16 < 4; n16++) {
                unsigned r0, r1, r2, r3;
                ldsm4(r0, r1, r2, r3,
                      kaddr + n16 * 16 * (AST * 2) + k16 * 32);
                mma16(S[2 * n16    ], Qf[k16], r0, r1);
                mma16(S[2 * n16 + 1], Qf[k16], r2, r3);
            }

        if (kt >= 2 * qt) {
            const int rg0 = qt * 128 + wb + lg, rg1 = rg0 + 8;
            #pragma unroll
            for (int nt = 0; nt < 8; nt++) {
                const int cg = kt * 64 + nt * 8 + 2 * la3;
                if (cg     > rg0) S[nt][0] = NEG_INF;
                if (cg + 1 > rg0) S[nt][1] = NEG_INF;
                if (cg     > rg1) S[nt][2] = NEG_INF;
                if (cg + 1 > rg1) S[nt][3] = NEG_INF;
            }
        }

        float mx0 = NEG_INF, mx1 = NEG_INF;
        #pragma unroll
        for (int nt = 0; nt < 8; nt++) {
            mx0 = fmaxf(mx0, fmaxf(S[nt][0], S[nt][1]));
            mx1 = fmaxf(mx1, fmaxf(S[nt][2], S[nt][3]));
        }
        mx0 = fmaxf(mx0, __shfl_xor_sync(0xffffffffu, mx0, 1));
        mx0 = fmaxf(mx0, __shfl_xor_sync(0xffffffffu, mx0, 2));
        mx1 = fmaxf(mx1, __shfl_xor_sync(0xffffffffu, mx1, 1));
        mx1 = fmaxf(mx1, __shfl_xor_sync(0xffffffffu, mx1, 2));
        const float mn0 = fmaxf(m0, mx0), mn1 = fmaxf(m1, mx1);
        const float al0 = ex2f(m0 - mn0), al1 = ex2f(m1 - mn1);
        m0 = mn0;  m1 = mn1;

        unsigned Pf[4][4];
        #pragma unroll
        for (int k16 = 0; k16 < 4; k16++) {
            Pf[k16][0] = hex2(pack2(S[2*k16  ][0] - mn0, S[2*k16  ][1] - mn0));
            Pf[k16][1] = hex2(pack2(S[2*k16  ][2] - mn1, S[2*k16  ][3] - mn1));
            Pf[k16][2] = hex2(pack2(S[2*k16+1][0] - mn0, S[2*k16+1][1] - mn0));
            Pf[k16][3] = hex2(pack2(S[2*k16+1][2] - mn1, S[2*k16+1][3] - mn1));
        }

        float ssum[4] = {0.f, 0.f, 0.f, 0.f};
        #pragma unroll
        for (int k16 = 0; k16 < 4; k16++)
            mma16(ssum, Pf[k16], ONES2, ONES2);
        l0 = l0 * al0 + ssum[0];
        l1 = l1 * al1 + ssum[2];

        #pragma unroll
        for (int nt = 0; nt < 8; nt++) {
            O[nt][0] *= al0;  O[nt][1] *= al0;
            O[nt][2] *= al1;  O[nt][3] *= al1;
        }

        #pragma unroll
        for (int k16 = 0; k16 < 4; k16++)
            #pragma unroll
            for (int n16 = 0; n16 < 4; n16++) {
                unsigned r0, r1, r2, r3;
                ldsm4t(r0, r1, r2, r3,
                       vaddr + k16 * 16 * (AST * 2) + n16 * 32);
                mma16(O[2 * n16    ], Pf[k16], r0, r1);
                mma16(O[2 * n16 + 1], Pf[k16], r2, r3);
            }

        if (++cur == 3) cur = 0;
    }

    __half* Og = Ob + base + (size_t)(qt * 128) * DM;
    const float il0 = 1.0f / l0, il1 = 1.0f / l1;
    const int r0 = wb + lg, r1 = r0 + 8;
    #pragma unroll
    for (int nt = 0; nt < 8; nt++) {
        const int col = nt * 8 + 2 * la3;
        *(unsigned*)&Og[(size_t)r0 * DM + col] =
            pack2(O[nt][0] * il0, O[nt][1] * il0);
        *(unsigned*)&Og[(size_t)r1 * DM + col] =
            pack2(O[nt][2] * il1, O[nt][3] * il1);
    }
}

// ---------------------------------------------------------------------------
extern "C" void kernel_launch(void* const* d_in, const int* in_sizes, int n_in,
                              void* d_out, int out_size)
{
    const float* x  = (const float*)d_in[0];
    const float* Ww = (const float*)d_in[1];
    const float* Wb = (const float*)d_in[2];
    const float* Ow = (const float*)d_in[3];
    const float* Ob = (const float*)d_in[4];
    float* out = (float*)d_out;

    __half *q, *k, *v, *c1, *c2, *xh, *wh, *oh;
    cudaGetSymbolAddress((void**)&q,  g_q);
    cudaGetSymbolAddress((void**)&k,  g_k);
    cudaGetSymbolAddress((void**)&v,  g_v);
    cudaGetSymbolAddress((void**)&c1, g_c1);
    cudaGetSymbolAddress((void**)&c2, g_c2);
    cudaGetSymbolAddress((void**)&xh, g_xh);
    cudaGetSymbolAddress((void**)&wh, g_wh);
    cudaGetSymbolAddress((void**)&oh, g_oh);

    cudaFuncSetAttribute(attn_h,
                         cudaFuncAttributeMaxDynamicSharedMemorySize, ATTN_SMEM);
    cudaFuncSetAttribute(gemm_hh<0>,
                         cudaFuncAttributeMaxDynamicSharedMemorySize, GEMM_SMEM);
    cudaFuncSetAttribute(gemm_hh<1>,
                         cudaFuncAttributeMaxDynamicSharedMemorySize, GEMM_SMEM);

    // 0) one-time fp16 conversions (single fused launch)
    f2h3<<<(N_X + N_W + N_O) / 2048, 256>>>(x, xh, Ww, wh, Ow, oh);

    // 1) QKV projection + bias -> fp16 q/k/v (k pre-scaled by log2e/8)
    dim3 g1(3 * DM / 128, MROWS / 128);
    gemm_hh<1><<<g1, 256, GEMM_SMEM>>>(xh, wh, Wb, nullptr,
                                       MROWS, 3 * DM, DM, q, k, v);

    // 2-4) repeated causal attention (fp16 in/out)
    dim3 ga(SEQ / 128, NH, BATCH);
    attn_h<<<ga, 256, ATTN_SMEM>>>(q,  k, v, c1);
    attn_h<<<ga, 256, ATTN_SMEM>>>(c1, k, v, c2);
    attn_h<<<ga, 256, ATTN_SMEM>>>(c2, k, v, c1);

    // 5) output projection + bias (f32 out)
    dim3 g2(DM / 128, MROWS / 128);
    gemm_hh<0><<<g2, 256, GEMM_SMEM>>>(c1, oh, Ob, out, MROWS, DM, DM,
                                       nullptr, nullptr, nullptr);
}